// round 10
// baseline (speedup 1.0000x reference)
#include <cuda_runtime.h>
#include <cuda_bf16.h>

#define Hdim 512
#define Wdim 512
#define Qn 3
#define Pn 1024
#define Bn 64
#define JITTER 1e-6f

#define TS 18      // strip/row stride in float2 (16B-aligned strip bases)
#define REG 296    // float2 per group region

typedef unsigned long long u64;

// ---- f32x2 packed helpers: u64 = (float lo = re, float hi = im) ----
__device__ __forceinline__ u64 pk2(float lo, float hi) {
    u64 d; asm("mov.b64 %0, {%1, %2};" : "=l"(d) : "f"(lo), "f"(hi)); return d;
}
__device__ __forceinline__ void upk2(u64 v, float& lo, float& hi) {
    asm("mov.b64 {%0, %1}, %2;" : "=f"(lo), "=f"(hi) : "l"(v));
}
__device__ __forceinline__ u64 add2(u64 a, u64 b) {
    u64 d; asm("add.rn.f32x2 %0, %1, %2;" : "=l"(d) : "l"(a), "l"(b)); return d;
}
__device__ __forceinline__ u64 mul2(u64 a, u64 b) {
    u64 d; asm("mul.rn.f32x2 %0, %1, %2;" : "=l"(d) : "l"(a), "l"(b)); return d;
}
__device__ __forceinline__ u64 fma2(u64 a, u64 b, u64 c) {
    u64 d; asm("fma.rn.f32x2 %0, %1, %2, %3;" : "=l"(d) : "l"(a), "l"(b), "l"(c)); return d;
}
__device__ __forceinline__ u64 sub2(u64 a, u64 b) {
    return fma2(b, pk2(-1.0f, -1.0f), a);
}
__device__ __forceinline__ u64 swp2(u64 v) {
    float a, b; upk2(v, a, b); return pk2(b, a);
}

// ---------------------------------------------------------------------------
// Packed 16-point complex FFT on AoS f32x2 values. DIR=-1 fwd, +1 inv.
// ---------------------------------------------------------------------------
template<int DIR>
__device__ __forceinline__ void fft16p(u64 z[16]) {
#define SWAPZ(a,b) { u64 _t = z[a]; z[a] = z[b]; z[b] = _t; }
    SWAPZ(1, 8) SWAPZ(2, 4) SWAPZ(3, 12) SWAPZ(5, 10) SWAPZ(7, 14) SWAPZ(11, 13)
#undef SWAPZ

#define BFLY(A, B, C, SN) { \
    u64 _t = fma2(swp2(z[B]), pk2(-(SN), (SN)), mul2(z[B], pk2((C), (C)))); \
    z[B] = sub2(z[A], _t);  z[A] = add2(z[A], _t); }

#define BFLY1(A, B) { \
    u64 _t = z[B];  z[B] = sub2(z[A], _t);  z[A] = add2(z[A], _t); }

#define BFLYI(A, B) { \
    u64 _t = mul2(swp2(z[B]), (DIR < 0) ? pk2(1.0f, -1.0f) : pk2(-1.0f, 1.0f)); \
    z[B] = sub2(z[A], _t);  z[A] = add2(z[A], _t); }

    const float R2  = 0.7071067811865476f;
    const float CT1 = 0.9238795325112867f;
    const float ST1 = 0.3826834323650898f;

    BFLY1(0,1)  BFLY1(2,3)  BFLY1(4,5)  BFLY1(6,7)
    BFLY1(8,9)  BFLY1(10,11) BFLY1(12,13) BFLY1(14,15)

    BFLY1(0,2)  BFLYI(1,3)
    BFLY1(4,6)  BFLYI(5,7)
    BFLY1(8,10) BFLYI(9,11)
    BFLY1(12,14) BFLYI(13,15)

    BFLY1(0,4)  BFLY(1,5,  R2, (float)DIR * R2)  BFLYI(2,6)  BFLY(3,7,  -R2, (float)DIR * R2)
    BFLY1(8,12) BFLY(9,13, R2, (float)DIR * R2)  BFLYI(10,14) BFLY(11,15, -R2, (float)DIR * R2)

    BFLY1(0,8)
    BFLY(1,9,   CT1, (float)DIR * ST1)
    BFLY(2,10,  R2,  (float)DIR * R2)
    BFLY(3,11,  ST1, (float)DIR * CT1)
    BFLYI(4,12)
    BFLY(5,13, -ST1, (float)DIR * CT1)
    BFLY(6,14, -R2,  (float)DIR * R2)
    BFLY(7,15, -CT1, (float)DIR * ST1)

#undef BFLY
#undef BFLY1
#undef BFLYI
}

// ---------------------------------------------------------------------------
// Single fused kernel: block = one adjacent patch pair (A,B) x 16 batches.
// S_sym computed in-block from separable Gaussian axis tables:
//   non-Nyquist: S_sym == S bit-exactly (f(-k) = -f(k));
//   Nyquist line ky=8: S_sym[8][kx] = 0.5*sum_q w*(g1y8+g2y8)(g1x+g2x)
//   Nyquist line kx=8: symmetric; (8,8): plain S.
// ---------------------------------------------------------------------------
__global__ __launch_bounds__(256, 4) void patch_spectral_kernel(
    const float* __restrict__ x,
    const float* __restrict__ logits,
    const float* __restrict__ mu,
    const float* __restrict__ sigma,
    const float* __restrict__ bias,
    float* __restrict__ y)
{
    __shared__ __align__(16) float2 colbuf[16][REG];
    __shared__ float sSt[2][336];        // transposed S_sym/256: sSt[h][kx*20+ky]
    __shared__ float gyx[2][2][6][16];   // [patch][axis(0=y,1=x)][qs][k]
    __shared__ float w2[2][4];           // softmax weights per patch

    const int pp = blockIdx.x & 511;
    const int bg = blockIdx.x >> 9;
    const int t  = threadIdx.x;
    const int p0 = pp * 2;

    const int wrp = t >> 5;
    const int l   = t & 31;
    const int g0  = wrp * 2;
    const int py  = p0 >> 5;
    const int px0 = p0 & 31;

    float* ss = (float*)colbuf;

    // ---- issue all x loads first (8-deep MLP over block startup) ----
    const int seg = l >> 3;
    const int c4  = (l & 7) * 4;
    float4 xrg[8];
#pragma unroll
    for (int i = 0; i < 8; ++i) {
        const int q   = i * 4 + seg;
        const int gof = q >> 4;
        const int r   = q & 15;
        const int b   = bg * 16 + g0 + gof;
        xrg[i] = *(const float4*)(x + (size_t)b * (Hdim * Wdim)
                                    + (size_t)(py * 16 + r) * Wdim
                                    + px0 * 16 + c4);
    }

    // ---- build axis tables (overlapped with x loads in flight) ----
    if (t < 2) {
        const int p = p0 + t;
        const float l0 = logits[p * Qn + 0];
        const float l1 = logits[p * Qn + 1];
        const float l2 = logits[p * Qn + 2];
        const float mx = fmaxf(l0, fmaxf(l1, l2));
        const float e0 = expf(l0 - mx);
        const float e1 = expf(l1 - mx);
        const float e2 = expf(l2 - mx);
        const float inv = 1.0f / (e0 + e1 + e2);
        w2[t][0] = e0 * inv; w2[t][1] = e1 * inv; w2[t][2] = e2 * inv;
    }
    {
        // 384 axis tasks over 256 threads
#pragma unroll
        for (int pass = 0; pass < 2; ++pass) {
            const int tau = t + pass * 256;
            if (pass == 1 && t >= 128) break;
            const int hh   = tau / 192;
            const int r    = tau % 192;
            const int axis = r / 96;
            const int rem  = r % 96;
            const int qs   = rem >> 4;
            const int k    = rem & 15;
            const int q    = qs >> 1;
            const int sgn  = qs & 1;
            const float f  = (float)(k < 8 ? k : k - 16) * (1.0f / 16.0f);
            const int base = ((p0 + hh) * Qn + q) * 2;
            const float m  = mu[base + axis];
            const float sg = sigma[base + axis];
            const float d  = (sgn ? (f + m) : (f - m)) / sg;
            gyx[hh][axis][qs][k] = expf(-0.5f * d * d);
        }
    }
    __syncthreads();

    // ---- compute S_sym/256 for this thread's (ky,kx), both patches ----
    {
        const int ky = t >> 4;
        const int kx = t & 15;
#pragma unroll
        for (int hh = 0; hh < 2; ++hh) {
            const float* gy = &gyx[hh][0][0][0];
            const float* gx = &gyx[hh][1][0][0];
            float s = 0.0f;
            if (ky != 8 && kx != 8) {
#pragma unroll
                for (int q = 0; q < Qn; ++q)
                    s += w2[hh][q] * (gy[(2*q)*16 + ky] * gx[(2*q)*16 + kx] +
                                      gy[(2*q+1)*16 + ky] * gx[(2*q+1)*16 + kx]);
            } else if (ky == 8 && kx == 8) {
#pragma unroll
                for (int q = 0; q < Qn; ++q)
                    s += w2[hh][q] * (gy[(2*q)*16 + 8] * gx[(2*q)*16 + 8] +
                                      gy[(2*q+1)*16 + 8] * gx[(2*q+1)*16 + 8]);
            } else if (ky == 8) {
#pragma unroll
                for (int q = 0; q < Qn; ++q)
                    s += w2[hh][q] * (gy[(2*q)*16 + 8] + gy[(2*q+1)*16 + 8]) *
                                     (gx[(2*q)*16 + kx] + gx[(2*q+1)*16 + kx]);
                s *= 0.5f;
            } else { // kx == 8
#pragma unroll
                for (int q = 0; q < Qn; ++q)
                    s += w2[hh][q] * (gy[(2*q)*16 + ky] + gy[(2*q+1)*16 + ky]) *
                                     (gx[(2*q)*16 + 8] + gx[(2*q+1)*16 + 8]);
                s *= 0.5f;
            }
            sSt[hh][kx * 20 + ky] = (s + JITTER) * (1.0f / 256.0f);
        }
    }

    // ---- stage x (coalesced registers -> smem) ----
#pragma unroll
    for (int i = 0; i < 8; ++i) {
        const int q   = i * 4 + seg;
        const int gof = q >> 4;
        const int r   = q & 15;
        *(float4*)(ss + (g0 + gof) * (2 * REG) + r * 36 + c4) = xrg[i];
    }
    __syncthreads();   // sSt visible block-wide; stage visible to own warp

    const int g  = g0 + (l >> 4);
    const int ln = l & 15;
    float2* buf = colbuf[g];
    float* srow = ss + g * (2 * REG) + ln * 36;

    u64 z[16];

    // ---- phase 1: pack rows A,B as complex AoS, packed row FFT ----
#pragma unroll
    for (int qq = 0; qq < 4; ++qq) {
        float4 va = *(const float4*)(srow + qq * 4);
        float4 vb = *(const float4*)(srow + 16 + qq * 4);
        z[qq*4+0] = pk2(va.x, vb.x);
        z[qq*4+1] = pk2(va.y, vb.y);
        z[qq*4+2] = pk2(va.z, vb.z);
        z[qq*4+3] = pk2(va.w, vb.w);
    }
    fft16p<-1>(z);

    // Hermitian unpack, store strip-major
    {
        float r0, i0, r8, i8;
        upk2(z[0], r0, i0);
        upk2(z[8], r8, i8);
        buf[0 * TS + ln]       = make_float2(r0, r8);   // A: (X[r,0], X[r,8])
        buf[(8 + 0) * TS + ln] = make_float2(i0, i8);   // B
    }
#pragma unroll
    for (int k = 1; k <= 7; ++k) {
        const int m = 16 - k;
        const u64 conjm = mul2(z[m], pk2(1.0f, -1.0f));
        const u64 XA = mul2(add2(z[k], conjm), pk2(0.5f, 0.5f));
        const u64 d  = sub2(z[k], conjm);
        const u64 XB = mul2(swp2(d), pk2(0.5f, -0.5f));
        *reinterpret_cast<u64*>(buf + k * TS + ln)       = XA;
        *reinterpret_cast<u64*>(buf + (8 + k) * TS + ln) = XB;
    }
    __syncwarp();

    // ---- phase 2: column task (tile = ln>>3, tt = ln&7) ----
    {
        const int tile = ln >> 3;
        const int tt   = ln & 7;
        const ulonglong2* sp2 = (const ulonglong2*)(buf + ln * TS);
#pragma unroll
        for (int q2 = 0; q2 < 8; ++q2) {
            const ulonglong2 v = sp2[q2];
            z[q2*2+0] = v.x;
            z[q2*2+1] = v.y;
        }

        fft16p<-1>(z);

        const float* Sp = sSt[tile];
        if (tt == 0) {
            // packed real cols 0 & 8: S[ky,0]=Sp[ky], S[ky,8]=Sp[160+ky]
#pragma unroll
            for (int ky = 0; ky <= 8; ++ky) {
                const int m = (16 - ky) & 15;
                const u64 conjv = mul2(z[m], pk2(1.0f, -1.0f));
                const u64 C0 = mul2(add2(z[ky], conjv), pk2(0.5f, 0.5f));
                const u64 w1 = sub2(z[ky], conjv);
                const u64 C8 = mul2(swp2(w1), pk2(0.5f, -0.5f));
                const float s0 = Sp[ky];
                const float s8 = Sp[160 + ky];
                const u64 A  = mul2(C0, pk2(s0, s0));
                const u64 B8 = mul2(C8, pk2(s8, s8));
                const u64 iB = mul2(swp2(B8), pk2(-1.0f, 1.0f));   // i*B8
                z[ky] = add2(A, iB);
                if (m != ky)
                    z[m] = mul2(sub2(A, iB), pk2(1.0f, -1.0f));    // conj(A - i*B8)
            }
        } else {
            const float4* Sc = (const float4*)(Sp + tt * 20);
#pragma unroll
            for (int q2 = 0; q2 < 4; ++q2) {
                const float4 s4 = Sc[q2];
                z[q2*4+0] = mul2(z[q2*4+0], pk2(s4.x, s4.x));
                z[q2*4+1] = mul2(z[q2*4+1], pk2(s4.y, s4.y));
                z[q2*4+2] = mul2(z[q2*4+2], pk2(s4.z, s4.z));
                z[q2*4+3] = mul2(z[q2*4+3], pk2(s4.w, s4.w));
            }
        }

        fft16p<1>(z);

        __syncwarp();   // all lanes done READING strips before overwrite
#pragma unroll
        for (int r = 0; r < 16; ++r)
            *reinterpret_cast<u64*>(buf + r * TS + ln) = z[r];
    }
    __syncwarp();

    // ---- phase 3: Hermitian-extend W rows (packed), inverse row FFT ----
    {
        u64 wrow[16];
        const ulonglong2* rp2 = (const ulonglong2*)(buf + ln * TS);
#pragma unroll
        for (int q2 = 0; q2 < 8; ++q2) {
            const ulonglong2 v = rp2[q2];
            wrow[q2*2+0] = v.x;
            wrow[q2*2+1] = v.y;
        }
        {
            float a0x, a0y, b0x, b0y;
            upk2(wrow[0], a0x, a0y);
            upk2(wrow[8], b0x, b0y);
            z[0] = pk2(a0x, b0x);
            z[8] = pk2(a0y, b0y);
        }
#pragma unroll
        for (int k = 1; k <= 7; ++k) {
            const u64 Wa = wrow[k];
            const u64 Wb = wrow[8 + k];
            const u64 iWb = mul2(swp2(Wb), pk2(-1.0f, 1.0f));      // i*W_B
            z[k]      = add2(Wa, iWb);                              // W_A + i W_B
            z[16 - k] = mul2(sub2(Wa, iWb), pk2(1.0f, -1.0f));      // conj(W_A - i W_B)
        }
    }
    fft16p<1>(z);

    // ---- epilogue: unpack, +bias (direct global), store into stage ----
    {
        float yA[16], yB[16];
#pragma unroll
        for (int j = 0; j < 16; ++j) upk2(z[j], yA[j], yB[j]);

        const float* bp = bias + p0 * 256 + ln * 16;
#pragma unroll
        for (int j = 0; j < 16; j += 4) {
            const float4 ba = *(const float4*)(bp + j);
            const float4 bb = *(const float4*)(bp + 256 + j);
            float4 oa, ob;
            oa.x = yA[j+0] + ba.x;  oa.y = yA[j+1] + ba.y;
            oa.z = yA[j+2] + ba.z;  oa.w = yA[j+3] + ba.w;
            ob.x = yB[j+0] + bb.x;  ob.y = yB[j+1] + bb.y;
            ob.z = yB[j+2] + bb.z;  ob.w = yB[j+3] + bb.w;
            *(float4*)(srow + j)      = oa;
            *(float4*)(srow + 16 + j) = ob;
        }
    }
    __syncwarp();

    // ---- staged coalesced store: 8 x STG.128, full sectors ----
#pragma unroll
    for (int i = 0; i < 8; ++i) {
        const int q   = i * 4 + seg;
        const int gof = q >> 4;
        const int r   = q & 15;
        const int gg  = g0 + gof;
        const int b   = bg * 16 + gg;
        float4 v = *(const float4*)(ss + gg * (2 * REG) + r * 36 + c4);
        *(float4*)(y + (size_t)b * (Hdim * Wdim)
                     + (size_t)(py * 16 + r) * Wdim
                     + px0 * 16 + c4) = v;
    }
}

extern "C" void kernel_launch(void* const* d_in, const int* in_sizes, int n_in,
                              void* d_out, int out_size)
{
    const float* x      = (const float*)d_in[0];
    const float* logits = (const float*)d_in[1];
    const float* mu     = (const float*)d_in[2];
    const float* sigma  = (const float*)d_in[3];
    const float* bias   = (const float*)d_in[4];
    float* y = (float*)d_out;

    patch_spectral_kernel<<<2048, 256>>>(x, logits, mu, sigma, bias, y);
}

// round 11
// speedup vs baseline: 1.2177x; 1.2177x over previous
#include <cuda_runtime.h>
#include <cuda_bf16.h>

#define Hdim 512
#define Wdim 512
#define Qn 3
#define Pn 1024
#define Bn 64
#define JITTER 1e-6f

#define TS 18      // strip/row stride in float2 (16B-aligned strip bases)
#define REG 296    // float2 per group region

typedef unsigned long long u64;

// ---- f32x2 packed helpers: u64 = (float lo = re, float hi = im) ----
__device__ __forceinline__ u64 pk2(float lo, float hi) {
    u64 d; asm("mov.b64 %0, {%1, %2};" : "=l"(d) : "f"(lo), "f"(hi)); return d;
}
__device__ __forceinline__ void upk2(u64 v, float& lo, float& hi) {
    asm("mov.b64 {%0, %1}, %2;" : "=f"(lo), "=f"(hi) : "l"(v));
}
__device__ __forceinline__ u64 add2(u64 a, u64 b) {
    u64 d; asm("add.rn.f32x2 %0, %1, %2;" : "=l"(d) : "l"(a), "l"(b)); return d;
}
__device__ __forceinline__ u64 mul2(u64 a, u64 b) {
    u64 d; asm("mul.rn.f32x2 %0, %1, %2;" : "=l"(d) : "l"(a), "l"(b)); return d;
}
__device__ __forceinline__ u64 fma2(u64 a, u64 b, u64 c) {
    u64 d; asm("fma.rn.f32x2 %0, %1, %2, %3;" : "=l"(d) : "l"(a), "l"(b), "l"(c)); return d;
}
__device__ __forceinline__ u64 sub2(u64 a, u64 b) {
    return fma2(b, pk2(-1.0f, -1.0f), a);
}
__device__ __forceinline__ u64 swp2(u64 v) {
    float a, b; upk2(v, a, b); return pk2(b, a);
}

// Precomputed symmetrized spectrum: S_sym[p][ky*16+kx] / 256
__device__ float g_S[Pn * 256];

// ---------------------------------------------------------------------------
// Kernel A: build S per patch (separable Gaussians), index-symmetrized.
// ---------------------------------------------------------------------------
__global__ __launch_bounds__(256) void make_S_kernel(
    const float* __restrict__ logits,
    const float* __restrict__ mu,
    const float* __restrict__ sigma)
{
    __shared__ float w[4];
    __shared__ float gy[6][16];
    __shared__ float gx[6][16];
    __shared__ float sAcc[256];

    const int p = blockIdx.x;
    const int t = threadIdx.x;

    if (t == 0) {
        const float l0 = logits[p * Qn + 0];
        const float l1 = logits[p * Qn + 1];
        const float l2 = logits[p * Qn + 2];
        const float mx = fmaxf(l0, fmaxf(l1, l2));
        const float e0 = expf(l0 - mx);
        const float e1 = expf(l1 - mx);
        const float e2 = expf(l2 - mx);
        const float inv = 1.0f / (e0 + e1 + e2);
        w[0] = e0 * inv; w[1] = e1 * inv; w[2] = e2 * inv;
    }
    if (t < 192) {
        const int axis = t / 96;
        const int rem  = t % 96;
        const int qs   = rem >> 4;
        const int k    = rem & 15;
        const int q    = qs >> 1;
        const int sgn  = qs & 1;
        const float f  = (float)(k < 8 ? k : k - 16) * (1.0f / 16.0f);
        const int base = (p * Qn + q) * 2;
        const float m  = mu[base + axis];
        const float s  = sigma[base + axis];
        const float d  = (sgn ? (f + m) : (f - m)) / s;
        const float v  = expf(-0.5f * d * d);
        if (axis == 0) gy[qs][k] = v; else gx[qs][k] = v;
    }
    __syncthreads();

    const int ky = t >> 4;
    const int kx = t & 15;
    float acc = 0.0f;
#pragma unroll
    for (int q = 0; q < Qn; ++q) {
        acc += w[q] * (gy[2 * q][ky] * gx[2 * q][kx] +
                       gy[2 * q + 1][ky] * gx[2 * q + 1][kx]);
    }
    sAcc[t] = acc;
    __syncthreads();

    const int tm = (((16 - ky) & 15) << 4) | ((16 - kx) & 15);
    const float ssym = 0.5f * (sAcc[t] + sAcc[tm]) + JITTER;
    g_S[p * 256 + t] = ssym * (1.0f / 256.0f);
}

// ---------------------------------------------------------------------------
// Packed 16-point complex FFT on AoS f32x2 values. DIR=-1 fwd, +1 inv.
// ---------------------------------------------------------------------------
template<int DIR>
__device__ __forceinline__ void fft16p(u64 z[16]) {
#define SWAPZ(a,b) { u64 _t = z[a]; z[a] = z[b]; z[b] = _t; }
    SWAPZ(1, 8) SWAPZ(2, 4) SWAPZ(3, 12) SWAPZ(5, 10) SWAPZ(7, 14) SWAPZ(11, 13)
#undef SWAPZ

#define BFLY(A, B, C, SN) { \
    u64 _t = fma2(swp2(z[B]), pk2(-(SN), (SN)), mul2(z[B], pk2((C), (C)))); \
    z[B] = sub2(z[A], _t);  z[A] = add2(z[A], _t); }

#define BFLY1(A, B) { \
    u64 _t = z[B];  z[B] = sub2(z[A], _t);  z[A] = add2(z[A], _t); }

#define BFLYI(A, B) { \
    u64 _t = mul2(swp2(z[B]), (DIR < 0) ? pk2(1.0f, -1.0f) : pk2(-1.0f, 1.0f)); \
    z[B] = sub2(z[A], _t);  z[A] = add2(z[A], _t); }

    const float R2  = 0.7071067811865476f;
    const float CT1 = 0.9238795325112867f;
    const float ST1 = 0.3826834323650898f;

    BFLY1(0,1)  BFLY1(2,3)  BFLY1(4,5)  BFLY1(6,7)
    BFLY1(8,9)  BFLY1(10,11) BFLY1(12,13) BFLY1(14,15)

    BFLY1(0,2)  BFLYI(1,3)
    BFLY1(4,6)  BFLYI(5,7)
    BFLY1(8,10) BFLYI(9,11)
    BFLY1(12,14) BFLYI(13,15)

    BFLY1(0,4)  BFLY(1,5,  R2, (float)DIR * R2)  BFLYI(2,6)  BFLY(3,7,  -R2, (float)DIR * R2)
    BFLY1(8,12) BFLY(9,13, R2, (float)DIR * R2)  BFLYI(10,14) BFLY(11,15, -R2, (float)DIR * R2)

    BFLY1(0,8)
    BFLY(1,9,   CT1, (float)DIR * ST1)
    BFLY(2,10,  R2,  (float)DIR * R2)
    BFLY(3,11,  ST1, (float)DIR * CT1)
    BFLYI(4,12)
    BFLY(5,13, -ST1, (float)DIR * CT1)
    BFLY(6,14, -R2,  (float)DIR * R2)
    BFLY(7,15, -CT1, (float)DIR * ST1)

#undef BFLY
#undef BFLY1
#undef BFLYI
}

// ---------------------------------------------------------------------------
// Kernel B: block = one adjacent patch pair (A,B) x 16 batches.
// Round 11 = round 9 + bias staged to smem at startup (epilogue reads LDS
// instead of late LDG on the critical path).
// ---------------------------------------------------------------------------
__global__ __launch_bounds__(256, 4) void patch_spectral_kernel(
    const float* __restrict__ x,
    const float* __restrict__ bias,
    float* __restrict__ y)
{
    __shared__ __align__(16) float2 colbuf[16][REG];
    __shared__ float sSt[2][336];                  // transposed S: sSt[h][kx*20+ky]
    __shared__ __align__(16) float sB[2][320];     // bias rows: sB[h][i*20+j]

    const int pp = blockIdx.x & 511;
    const int bg = blockIdx.x >> 9;
    const int t  = threadIdx.x;
    const int p0 = pp * 2;

    const int wrp = t >> 5;
    const int l   = t & 31;
    const int g0  = wrp * 2;
    const int py  = p0 >> 5;
    const int px0 = p0 & 31;

    float* ss = (float*)colbuf;

    // ---- issue all x loads first (8-deep MLP over block startup) ----
    const int seg = l >> 3;
    const int c4  = (l & 7) * 4;
    float4 xrg[8];
#pragma unroll
    for (int i = 0; i < 8; ++i) {
        const int q   = i * 4 + seg;
        const int gof = q >> 4;
        const int r   = q & 15;
        const int b   = bg * 16 + g0 + gof;
        xrg[i] = *(const float4*)(x + (size_t)b * (Hdim * Wdim)
                                    + (size_t)(py * 16 + r) * Wdim
                                    + px0 * 16 + c4);
    }

    // ---- stage S (transposed) and bias while x loads are in flight ----
    {
        const int ky = t >> 4;   // also bias row i
        const int kx = t & 15;   // also bias col j
#pragma unroll
        for (int hh = 0; hh < 2; ++hh) {
            sSt[hh][kx * 20 + ky] = g_S[(p0 + hh) * 256 + t];
            sB[hh][ky * 20 + kx]  = bias[(p0 + hh) * 256 + t];
        }
    }
    __syncthreads();

    // ---- stage x (coalesced registers -> smem) ----
#pragma unroll
    for (int i = 0; i < 8; ++i) {
        const int q   = i * 4 + seg;
        const int gof = q >> 4;
        const int r   = q & 15;
        *(float4*)(ss + (g0 + gof) * (2 * REG) + r * 36 + c4) = xrg[i];
    }
    __syncwarp();

    const int g  = g0 + (l >> 4);
    const int ln = l & 15;
    float2* buf = colbuf[g];
    float* srow = ss + g * (2 * REG) + ln * 36;

    u64 z[16];

    // ---- phase 1: pack rows A,B as complex AoS, packed row FFT ----
#pragma unroll
    for (int qq = 0; qq < 4; ++qq) {
        float4 va = *(const float4*)(srow + qq * 4);
        float4 vb = *(const float4*)(srow + 16 + qq * 4);
        z[qq*4+0] = pk2(va.x, vb.x);
        z[qq*4+1] = pk2(va.y, vb.y);
        z[qq*4+2] = pk2(va.z, vb.z);
        z[qq*4+3] = pk2(va.w, vb.w);
    }
    fft16p<-1>(z);

    // Hermitian unpack, store strip-major
    {
        float r0, i0, r8, i8;
        upk2(z[0], r0, i0);
        upk2(z[8], r8, i8);
        buf[0 * TS + ln]       = make_float2(r0, r8);   // A: (X[r,0], X[r,8])
        buf[(8 + 0) * TS + ln] = make_float2(i0, i8);   // B
    }
#pragma unroll
    for (int k = 1; k <= 7; ++k) {
        const int m = 16 - k;
        const u64 conjm = mul2(z[m], pk2(1.0f, -1.0f));
        const u64 XA = mul2(add2(z[k], conjm), pk2(0.5f, 0.5f));
        const u64 d  = sub2(z[k], conjm);
        const u64 XB = mul2(swp2(d), pk2(0.5f, -0.5f));
        *reinterpret_cast<u64*>(buf + k * TS + ln)       = XA;
        *reinterpret_cast<u64*>(buf + (8 + k) * TS + ln) = XB;
    }
    __syncwarp();

    // ---- phase 2: column task (tile = ln>>3, tt = ln&7) ----
    {
        const int tile = ln >> 3;
        const int tt   = ln & 7;
        const ulonglong2* sp2 = (const ulonglong2*)(buf + ln * TS);
#pragma unroll
        for (int q2 = 0; q2 < 8; ++q2) {
            const ulonglong2 v = sp2[q2];
            z[q2*2+0] = v.x;
            z[q2*2+1] = v.y;
        }

        fft16p<-1>(z);

        const float* Sp = sSt[tile];
        if (tt == 0) {
            // packed real cols 0 & 8: S[ky,0]=Sp[ky], S[ky,8]=Sp[160+ky]
#pragma unroll
            for (int ky = 0; ky <= 8; ++ky) {
                const int m = (16 - ky) & 15;
                const u64 conjv = mul2(z[m], pk2(1.0f, -1.0f));
                const u64 C0 = mul2(add2(z[ky], conjv), pk2(0.5f, 0.5f));
                const u64 w1 = sub2(z[ky], conjv);
                const u64 C8 = mul2(swp2(w1), pk2(0.5f, -0.5f));
                const float s0 = Sp[ky];
                const float s8 = Sp[160 + ky];
                const u64 A  = mul2(C0, pk2(s0, s0));
                const u64 B8 = mul2(C8, pk2(s8, s8));
                const u64 iB = mul2(swp2(B8), pk2(-1.0f, 1.0f));   // i*B8
                z[ky] = add2(A, iB);
                if (m != ky)
                    z[m] = mul2(sub2(A, iB), pk2(1.0f, -1.0f));    // conj(A - i*B8)
            }
        } else {
            const float4* Sc = (const float4*)(Sp + tt * 20);
#pragma unroll
            for (int q2 = 0; q2 < 4; ++q2) {
                const float4 s4 = Sc[q2];
                z[q2*4+0] = mul2(z[q2*4+0], pk2(s4.x, s4.x));
                z[q2*4+1] = mul2(z[q2*4+1], pk2(s4.y, s4.y));
                z[q2*4+2] = mul2(z[q2*4+2], pk2(s4.z, s4.z));
                z[q2*4+3] = mul2(z[q2*4+3], pk2(s4.w, s4.w));
            }
        }

        fft16p<1>(z);

        __syncwarp();   // all lanes done READING strips before overwrite
#pragma unroll
        for (int r = 0; r < 16; ++r)
            *reinterpret_cast<u64*>(buf + r * TS + ln) = z[r];
    }
    __syncwarp();

    // ---- phase 3: Hermitian-extend W rows (packed), inverse row FFT ----
    {
        u64 wrow[16];
        const ulonglong2* rp2 = (const ulonglong2*)(buf + ln * TS);
#pragma unroll
        for (int q2 = 0; q2 < 8; ++q2) {
            const ulonglong2 v = rp2[q2];
            wrow[q2*2+0] = v.x;
            wrow[q2*2+1] = v.y;
        }
        {
            float a0x, a0y, b0x, b0y;
            upk2(wrow[0], a0x, a0y);
            upk2(wrow[8], b0x, b0y);
            z[0] = pk2(a0x, b0x);
            z[8] = pk2(a0y, b0y);
        }
#pragma unroll
        for (int k = 1; k <= 7; ++k) {
            const u64 Wa = wrow[k];
            const u64 Wb = wrow[8 + k];
            const u64 iWb = mul2(swp2(Wb), pk2(-1.0f, 1.0f));      // i*W_B
            z[k]      = add2(Wa, iWb);                              // W_A + i W_B
            z[16 - k] = mul2(sub2(Wa, iWb), pk2(1.0f, -1.0f));      // conj(W_A - i W_B)
        }
    }
    fft16p<1>(z);

    // ---- epilogue: unpack, +bias (from smem), store into stage ----
    {
        float yA[16], yB[16];
#pragma unroll
        for (int j = 0; j < 16; ++j) upk2(z[j], yA[j], yB[j]);

        const float* bA = sB[0] + ln * 20;
        const float* bB = sB[1] + ln * 20;
#pragma unroll
        for (int j = 0; j < 16; j += 4) {
            const float4 ba = *(const float4*)(bA + j);
            const float4 bb = *(const float4*)(bB + j);
            float4 oa, ob;
            oa.x = yA[j+0] + ba.x;  oa.y = yA[j+1] + ba.y;
            oa.z = yA[j+2] + ba.z;  oa.w = yA[j+3] + ba.w;
            ob.x = yB[j+0] + bb.x;  ob.y = yB[j+1] + bb.y;
            ob.z = yB[j+2] + bb.z;  ob.w = yB[j+3] + bb.w;
            *(float4*)(srow + j)      = oa;
            *(float4*)(srow + 16 + j) = ob;
        }
    }
    __syncwarp();

    // ---- staged coalesced store: 8 x STG.128, full sectors ----
#pragma unroll
    for (int i = 0; i < 8; ++i) {
        const int q   = i * 4 + seg;
        const int gof = q >> 4;
        const int r   = q & 15;
        const int gg  = g0 + gof;
        const int b   = bg * 16 + gg;
        float4 v = *(const float4*)(ss + gg * (2 * REG) + r * 36 + c4);
        *(float4*)(y + (size_t)b * (Hdim * Wdim)
                     + (size_t)(py * 16 + r) * Wdim
                     + px0 * 16 + c4) = v;
    }
}

extern "C" void kernel_launch(void* const* d_in, const int* in_sizes, int n_in,
                              void* d_out, int out_size)
{
    const float* x      = (const float*)d_in[0];
    const float* logits = (const float*)d_in[1];
    const float* mu     = (const float*)d_in[2];
    const float* sigma  = (const float*)d_in[3];
    const float* bias   = (const float*)d_in[4];
    float* y = (float*)d_out;

    make_S_kernel<<<Pn, 256>>>(logits, mu, sigma);
    patch_spectral_kernel<<<2048, 256>>>(x, bias, y);
}

// round 12
// speedup vs baseline: 1.2971x; 1.0652x over previous
#include <cuda_runtime.h>
#include <cuda_bf16.h>

#define Hdim 512
#define Wdim 512
#define Qn 3
#define Pn 1024
#define Bn 64
#define JITTER 1e-6f

#define TS 18      // strip/row stride in float2 (16B-aligned strip bases)
#define REG 296    // float2 per group region

typedef unsigned long long u64;

// ---- f32x2 packed helpers: u64 = (float lo = re, float hi = im) ----
__device__ __forceinline__ u64 pk2(float lo, float hi) {
    u64 d; asm("mov.b64 %0, {%1, %2};" : "=l"(d) : "f"(lo), "f"(hi)); return d;
}
__device__ __forceinline__ void upk2(u64 v, float& lo, float& hi) {
    asm("mov.b64 {%0, %1}, %2;" : "=f"(lo), "=f"(hi) : "l"(v));
}
__device__ __forceinline__ u64 add2(u64 a, u64 b) {
    u64 d; asm("add.rn.f32x2 %0, %1, %2;" : "=l"(d) : "l"(a), "l"(b)); return d;
}
__device__ __forceinline__ u64 mul2(u64 a, u64 b) {
    u64 d; asm("mul.rn.f32x2 %0, %1, %2;" : "=l"(d) : "l"(a), "l"(b)); return d;
}
__device__ __forceinline__ u64 fma2(u64 a, u64 b, u64 c) {
    u64 d; asm("fma.rn.f32x2 %0, %1, %2, %3;" : "=l"(d) : "l"(a), "l"(b), "l"(c)); return d;
}
__device__ __forceinline__ u64 sub2(u64 a, u64 b) {
    return fma2(b, pk2(-1.0f, -1.0f), a);
}
__device__ __forceinline__ u64 swp2(u64 v) {
    float a, b; upk2(v, a, b); return pk2(b, a);
}

// Precomputed symmetrized spectrum: S_sym[p][ky*16+kx] / 256
__device__ float g_S[Pn * 256];

// ---------------------------------------------------------------------------
// Kernel A (lean): direct S_sym per thread (both mirror terms), one sync.
// ---------------------------------------------------------------------------
__global__ __launch_bounds__(256) void make_S_kernel(
    const float* __restrict__ logits,
    const float* __restrict__ mu,
    const float* __restrict__ sigma)
{
    __shared__ float w[4];
    __shared__ float gy[6][16];
    __shared__ float gx[6][16];

    const int p = blockIdx.x;
    const int t = threadIdx.x;

    if (t == 0) {
        const float l0 = logits[p * Qn + 0];
        const float l1 = logits[p * Qn + 1];
        const float l2 = logits[p * Qn + 2];
        const float mx = fmaxf(l0, fmaxf(l1, l2));
        const float e0 = expf(l0 - mx);
        const float e1 = expf(l1 - mx);
        const float e2 = expf(l2 - mx);
        const float inv = 1.0f / (e0 + e1 + e2);
        w[0] = e0 * inv; w[1] = e1 * inv; w[2] = e2 * inv;
    }
    if (t < 192) {
        const int axis = t / 96;
        const int rem  = t % 96;
        const int qs   = rem >> 4;
        const int k    = rem & 15;
        const int q    = qs >> 1;
        const int sgn  = qs & 1;
        const float f  = (float)(k < 8 ? k : k - 16) * (1.0f / 16.0f);
        const int base = (p * Qn + q) * 2;
        const float m  = mu[base + axis];
        const float s  = sigma[base + axis];
        const float d  = (sgn ? (f + m) : (f - m)) / s;
        const float v  = expf(-0.5f * d * d);
        if (axis == 0) gy[qs][k] = v; else gx[qs][k] = v;
    }
    __syncthreads();

    const int ky  = t >> 4;
    const int kx  = t & 15;
    const int kym = (16 - ky) & 15;
    const int kxm = (16 - kx) & 15;
    float a = 0.0f, b = 0.0f;
#pragma unroll
    for (int q = 0; q < Qn; ++q) {
        a += w[q] * (gy[2 * q][ky] * gx[2 * q][kx] +
                     gy[2 * q + 1][ky] * gx[2 * q + 1][kx]);
        b += w[q] * (gy[2 * q][kym] * gx[2 * q][kxm] +
                     gy[2 * q + 1][kym] * gx[2 * q + 1][kxm]);
    }
    const float ssym = 0.5f * (a + b) + JITTER;
    g_S[p * 256 + t] = ssym * (1.0f / 256.0f);
}

// ---------------------------------------------------------------------------
// Packed 16-point complex FFT on AoS f32x2 values. DIR=-1 fwd, +1 inv.
// ---------------------------------------------------------------------------
template<int DIR>
__device__ __forceinline__ void fft16p(u64 z[16]) {
#define SWAPZ(a,b) { u64 _t = z[a]; z[a] = z[b]; z[b] = _t; }
    SWAPZ(1, 8) SWAPZ(2, 4) SWAPZ(3, 12) SWAPZ(5, 10) SWAPZ(7, 14) SWAPZ(11, 13)
#undef SWAPZ

#define BFLY(A, B, C, SN) { \
    u64 _t = fma2(swp2(z[B]), pk2(-(SN), (SN)), mul2(z[B], pk2((C), (C)))); \
    z[B] = sub2(z[A], _t);  z[A] = add2(z[A], _t); }

#define BFLY1(A, B) { \
    u64 _t = z[B];  z[B] = sub2(z[A], _t);  z[A] = add2(z[A], _t); }

#define BFLYI(A, B) { \
    u64 _t = mul2(swp2(z[B]), (DIR < 0) ? pk2(1.0f, -1.0f) : pk2(-1.0f, 1.0f)); \
    z[B] = sub2(z[A], _t);  z[A] = add2(z[A], _t); }

    const float R2  = 0.7071067811865476f;
    const float CT1 = 0.9238795325112867f;
    const float ST1 = 0.3826834323650898f;

    BFLY1(0,1)  BFLY1(2,3)  BFLY1(4,5)  BFLY1(6,7)
    BFLY1(8,9)  BFLY1(10,11) BFLY1(12,13) BFLY1(14,15)

    BFLY1(0,2)  BFLYI(1,3)
    BFLY1(4,6)  BFLYI(5,7)
    BFLY1(8,10) BFLYI(9,11)
    BFLY1(12,14) BFLYI(13,15)

    BFLY1(0,4)  BFLY(1,5,  R2, (float)DIR * R2)  BFLYI(2,6)  BFLY(3,7,  -R2, (float)DIR * R2)
    BFLY1(8,12) BFLY(9,13, R2, (float)DIR * R2)  BFLYI(10,14) BFLY(11,15, -R2, (float)DIR * R2)

    BFLY1(0,8)
    BFLY(1,9,   CT1, (float)DIR * ST1)
    BFLY(2,10,  R2,  (float)DIR * R2)
    BFLY(3,11,  ST1, (float)DIR * CT1)
    BFLYI(4,12)
    BFLY(5,13, -ST1, (float)DIR * CT1)
    BFLY(6,14, -R2,  (float)DIR * R2)
    BFLY(7,15, -CT1, (float)DIR * ST1)

#undef BFLY
#undef BFLY1
#undef BFLYI
}

// ---------------------------------------------------------------------------
// Kernel B: round 11 + cp.async x-stage + S prefetched before phase-2 FFT.
// ---------------------------------------------------------------------------
__global__ __launch_bounds__(256, 4) void patch_spectral_kernel(
    const float* __restrict__ x,
    const float* __restrict__ bias,
    float* __restrict__ y)
{
    __shared__ __align__(16) float2 colbuf[16][REG];
    __shared__ float sSt[2][336];                  // transposed S: sSt[h][kx*20+ky]
    __shared__ __align__(16) float sB[2][320];     // bias rows: sB[h][i*20+j]

    const int pp = blockIdx.x & 511;
    const int bg = blockIdx.x >> 9;
    const int t  = threadIdx.x;
    const int p0 = pp * 2;

    const int wrp = t >> 5;
    const int l   = t & 31;
    const int g0  = wrp * 2;
    const int py  = p0 >> 5;
    const int px0 = p0 & 31;

    float* ss = (float*)colbuf;

    // ---- cp.async x -> stage (8 x LDGSTS.128 per thread, coalesced) ----
    const int seg = l >> 3;
    const int c4  = (l & 7) * 4;
#pragma unroll
    for (int i = 0; i < 8; ++i) {
        const int q   = i * 4 + seg;
        const int gof = q >> 4;
        const int r   = q & 15;
        const int b   = bg * 16 + g0 + gof;
        const float* gp = x + (size_t)b * (Hdim * Wdim)
                            + (size_t)(py * 16 + r) * Wdim
                            + px0 * 16 + c4;
        const unsigned sp = (unsigned)__cvta_generic_to_shared(
            ss + (g0 + gof) * (2 * REG) + r * 36 + c4);
        asm volatile("cp.async.ca.shared.global [%0], [%1], 16;"
                     :: "r"(sp), "l"(gp) : "memory");
    }
    asm volatile("cp.async.commit_group;" ::: "memory");

    // ---- stage S (transposed) and bias while copies are in flight ----
    {
        const int ky = t >> 4;   // also bias row i
        const int kx = t & 15;   // also bias col j
#pragma unroll
        for (int hh = 0; hh < 2; ++hh) {
            sSt[hh][kx * 20 + ky] = g_S[(p0 + hh) * 256 + t];
            sB[hh][ky * 20 + kx]  = bias[(p0 + hh) * 256 + t];
        }
    }
    asm volatile("cp.async.wait_group 0;" ::: "memory");
    __syncthreads();

    const int g  = g0 + (l >> 4);
    const int ln = l & 15;
    float2* buf = colbuf[g];
    float* srow = ss + g * (2 * REG) + ln * 36;

    u64 z[16];

    // ---- phase 1: pack rows A,B as complex AoS, packed row FFT ----
#pragma unroll
    for (int qq = 0; qq < 4; ++qq) {
        float4 va = *(const float4*)(srow + qq * 4);
        float4 vb = *(const float4*)(srow + 16 + qq * 4);
        z[qq*4+0] = pk2(va.x, vb.x);
        z[qq*4+1] = pk2(va.y, vb.y);
        z[qq*4+2] = pk2(va.z, vb.z);
        z[qq*4+3] = pk2(va.w, vb.w);
    }
    fft16p<-1>(z);

    // Hermitian unpack, store strip-major
    {
        float r0, i0, r8, i8;
        upk2(z[0], r0, i0);
        upk2(z[8], r8, i8);
        buf[0 * TS + ln]       = make_float2(r0, r8);   // A: (X[r,0], X[r,8])
        buf[(8 + 0) * TS + ln] = make_float2(i0, i8);   // B
    }
#pragma unroll
    for (int k = 1; k <= 7; ++k) {
        const int m = 16 - k;
        const u64 conjm = mul2(z[m], pk2(1.0f, -1.0f));
        const u64 XA = mul2(add2(z[k], conjm), pk2(0.5f, 0.5f));
        const u64 d  = sub2(z[k], conjm);
        const u64 XB = mul2(swp2(d), pk2(0.5f, -0.5f));
        *reinterpret_cast<u64*>(buf + k * TS + ln)       = XA;
        *reinterpret_cast<u64*>(buf + (8 + k) * TS + ln) = XB;
    }
    __syncwarp();

    // ---- phase 2: column task (tile = ln>>3, tt = ln&7) ----
    {
        const int tile = ln >> 3;
        const int tt   = ln & 7;
        const ulonglong2* sp2 = (const ulonglong2*)(buf + ln * TS);
#pragma unroll
        for (int q2 = 0; q2 < 8; ++q2) {
            const ulonglong2 v = sp2[q2];
            z[q2*2+0] = v.x;
            z[q2*2+1] = v.y;
        }

        // prefetch this task's S column into registers BEFORE the FFT
        const float* Sp = sSt[tile];
        float s_arr[16];
        {
            const float4* Sc = (const float4*)(Sp + tt * 20);
#pragma unroll
            for (int q2 = 0; q2 < 4; ++q2) {
                const float4 v = Sc[q2];
                s_arr[q2*4+0] = v.x;  s_arr[q2*4+1] = v.y;
                s_arr[q2*4+2] = v.z;  s_arr[q2*4+3] = v.w;
            }
        }

        fft16p<-1>(z);

        if (tt == 0) {
            // packed real cols 0 & 8: S[ky,0]=s_arr[ky], S[ky,8]=Sp[160+ky]
#pragma unroll
            for (int ky = 0; ky <= 8; ++ky) {
                const int m = (16 - ky) & 15;
                const u64 conjv = mul2(z[m], pk2(1.0f, -1.0f));
                const u64 C0 = mul2(add2(z[ky], conjv), pk2(0.5f, 0.5f));
                const u64 w1 = sub2(z[ky], conjv);
                const u64 C8 = mul2(swp2(w1), pk2(0.5f, -0.5f));
                const float s0 = s_arr[ky];
                const float s8 = Sp[160 + ky];
                const u64 A  = mul2(C0, pk2(s0, s0));
                const u64 B8 = mul2(C8, pk2(s8, s8));
                const u64 iB = mul2(swp2(B8), pk2(-1.0f, 1.0f));   // i*B8
                z[ky] = add2(A, iB);
                if (m != ky)
                    z[m] = mul2(sub2(A, iB), pk2(1.0f, -1.0f));    // conj(A - i*B8)
            }
        } else {
#pragma unroll
            for (int j = 0; j < 16; ++j)
                z[j] = mul2(z[j], pk2(s_arr[j], s_arr[j]));
        }

        fft16p<1>(z);

        __syncwarp();   // all lanes done READING strips before overwrite
#pragma unroll
        for (int r = 0; r < 16; ++r)
            *reinterpret_cast<u64*>(buf + r * TS + ln) = z[r];
    }
    __syncwarp();

    // ---- phase 3: Hermitian-extend W rows (packed), inverse row FFT ----
    {
        u64 wrow[16];
        const ulonglong2* rp2 = (const ulonglong2*)(buf + ln * TS);
#pragma unroll
        for (int q2 = 0; q2 < 8; ++q2) {
            const ulonglong2 v = rp2[q2];
            wrow[q2*2+0] = v.x;
            wrow[q2*2+1] = v.y;
        }
        {
            float a0x, a0y, b0x, b0y;
            upk2(wrow[0], a0x, a0y);
            upk2(wrow[8], b0x, b0y);
            z[0] = pk2(a0x, b0x);
            z[8] = pk2(a0y, b0y);
        }
#pragma unroll
        for (int k = 1; k <= 7; ++k) {
            const u64 Wa = wrow[k];
            const u64 Wb = wrow[8 + k];
            const u64 iWb = mul2(swp2(Wb), pk2(-1.0f, 1.0f));      // i*W_B
            z[k]      = add2(Wa, iWb);                              // W_A + i W_B
            z[16 - k] = mul2(sub2(Wa, iWb), pk2(1.0f, -1.0f));      // conj(W_A - i W_B)
        }
    }
    fft16p<1>(z);

    // ---- epilogue: unpack, +bias (from smem), store into stage ----
    {
        float yA[16], yB[16];
#pragma unroll
        for (int j = 0; j < 16; ++j) upk2(z[j], yA[j], yB[j]);

        const float* bA = sB[0] + ln * 20;
        const float* bB = sB[1] + ln * 20;
#pragma unroll
        for (int j = 0; j < 16; j += 4) {
            const float4 ba = *(const float4*)(bA + j);
            const float4 bb = *(const float4*)(bB + j);
            float4 oa, ob;
            oa.x = yA[j+0] + ba.x;  oa.y = yA[j+1] + ba.y;
            oa.z = yA[j+2] + ba.z;  oa.w = yA[j+3] + ba.w;
            ob.x = yB[j+0] + bb.x;  ob.y = yB[j+1] + bb.y;
            ob.z = yB[j+2] + bb.z;  ob.w = yB[j+3] + bb.w;
            *(float4*)(srow + j)      = oa;
            *(float4*)(srow + 16 + j) = ob;
        }
    }
    __syncwarp();

    // ---- staged coalesced store: 8 x STG.128, full sectors ----
#pragma unroll
    for (int i = 0; i < 8; ++i) {
        const int q   = i * 4 + seg;
        const int gof = q >> 4;
        const int r   = q & 15;
        const int gg  = g0 + gof;
        const int b   = bg * 16 + gg;
        float4 v = *(const float4*)(ss + gg * (2 * REG) + r * 36 + c4);
        *(float4*)(y + (size_t)b * (Hdim * Wdim)
                     + (size_t)(py * 16 + r) * Wdim
                     + px0 * 16 + c4) = v;
    }
}

extern "C" void kernel_launch(void* const* d_in, const int* in_sizes, int n_in,
                              void* d_out, int out_size)
{
    const float* x      = (const float*)d_in[0];
    const float* logits = (const float*)d_in[1];
    const float* mu     = (const float*)d_in[2];
    const float* sigma  = (const float*)d_in[3];
    const float* bias   = (const float*)d_in[4];
    float* y = (float*)d_out;

    make_S_kernel<<<Pn, 256>>>(logits, mu, sigma);
    patch_spectral_kernel<<<2048, 256>>>(x, bias, y);
}